// round 11
// baseline (speedup 1.0000x reference)
#include <cuda_runtime.h>
#include <stdint.h>

#define B       8
#define NH      778
#define VOBJ    40000
#define NTOT    (B * NH)          // 6224
#define THREADS 160               // 5 warps
#define HREG    5                 // 160*5 = 800 >= 778
#define OSLICES 74                // 74*8 = 592 blocks = exactly 4 per SM, one wave
#define OSLICE  544               // 74*544 = 40256 >= 40000 (tail clamp-padded)
#define NPAIRS  272               // compile-time trip count, 272 = 4*68
#define NBLOCKS (OSLICES * B)     // 592

__constant__ int c_contact_idx[10] = {745, 317, 444, 556, 673, 95, 182, 234, 279, 320};

// running min over slices, stored as COMPLEMENTED d^2 bits:
//   key = ~__float_as_uint(d2), d2 >= 0  ->  max(key) == min(d2)
// zero-initialized at module load; finalizer re-zeros after reading, so every
// graph replay starts clean.
__device__ unsigned int g_dmin[NTOT];
__device__ int g_ticket;           // zero-init; finalizer resets to 0

// ---- zero-cost f32x2 <-> double bitcasts (register aliasing, no MOV) ----
__device__ __forceinline__ double pk2(float lo, float hi) {
    return __hiloint2double(__float_as_int(hi), __float_as_int(lo));
}
__device__ __forceinline__ float lo2(double v) { return __int_as_float(__double2loint(v)); }
__device__ __forceinline__ float hi2(double v) { return __int_as_float(__double2hiint(v)); }
__device__ __forceinline__ double fma2(double a, double b, double c) {
    double d;
    asm("fma.rn.f32x2 %0, %1, %2, %3;" : "=d"(d) : "d"(a), "d"(b), "d"(c));
    return d;
}
// packed min via two scalar FMNMX on aliased halves (no packed f32 min on HW)
__device__ __forceinline__ double min2(double a, double b) {
    return pk2(fminf(lo2(a), lo2(b)), fminf(hi2(a), hi2(b)));
}

__global__ __launch_bounds__(THREADS, 4) void mindist_kernel(
    const float* __restrict__ hand, const float* __restrict__ obj,
    float* __restrict__ out)
{
    const int b     = blockIdx.z;
    const int slice = blockIdx.y;
    const int t     = threadIdx.x;

    // each thread owns HREG hand verts: h = t + k*THREADS (coalesced loads)
    double axx[HREG], ayy[HREG], azz[HREG];
    float asq[HREG];
    #pragma unroll
    for (int k = 0; k < HREG; k++) {
        int h  = t + k * THREADS;
        int hc = (h < NH) ? h : 0;          // clamp: spare lanes recompute vert 0
        const float* hp = hand + ((size_t)b * NH + hc) * 3;
        float ax = hp[0], ay = hp[1], az = hp[2];
        asq[k] = fmaf(ax, ax, fmaf(ay, ay, az * az));
        axx[k] = pk2(ax, ax);
        ayy[k] = pk2(ay, ay);
        azz[k] = pk2(az, az);
    }

    // packed-pair SoA: shA[p]={(-2x0,-2x1),(-2y0,-2y1)}, shB[p]={(-2z0,-2z1),(bsq0,bsq1)}
    __shared__ double2 shA[NPAIRS];
    __shared__ double2 shB[NPAIRS];

    const int o0 = slice * OSLICE;

    // tile fill (272 pairs / 160 threads = 2 rounds); pad-by-clamp
    for (int k = t; k < NPAIRS; k += THREADS) {
        int pidx = o0 + k * 2;
        pidx = (pidx <= VOBJ - 2) ? pidx : (VOBJ - 2);
        const float* op = obj + ((size_t)b * VOBJ + pidx) * 3;
        float2 p01 = *(const float2*)(op + 0);   // x0 y0
        float2 p23 = *(const float2*)(op + 2);   // z0 x1
        float2 p45 = *(const float2*)(op + 4);   // y1 z1
        float x0 = p01.x, y0 = p01.y, z0 = p23.x;
        float x1 = p23.y, y1 = p45.x, z1 = p45.y;
        float w0 = fmaf(x0, x0, fmaf(y0, y0, z0 * z0));
        float w1 = fmaf(x1, x1, fmaf(y1, y1, z1 * z1));
        double2 A, Bv;
        A.x  = pk2(-2.f * x0, -2.f * x1);
        A.y  = pk2(-2.f * y0, -2.f * y1);
        Bv.x = pk2(-2.f * z0, -2.f * z1);
        Bv.y = pk2(w0, w1);
        shA[k] = A;
        shB[k] = Bv;
    }
    __syncthreads();

    double mp[HREG];                         // packed running mins
    #pragma unroll
    for (int k = 0; k < HREG; k++) mp[k] = pk2(3.4e38f, 3.4e38f);

    // 4-wide window: hoisted loads, k-outer for operand reuse, 4 chains ILP
    for (int p = 0; p < NPAIRS; p += 4) {
        double2 A0 = shA[p + 0], B0 = shB[p + 0];
        double2 A1 = shA[p + 1], B1 = shB[p + 1];
        double2 A2 = shA[p + 2], B2 = shB[p + 2];
        double2 A3 = shA[p + 3], B3 = shB[p + 3];
        #pragma unroll
        for (int k = 0; k < HREG; k++) {
            double e0 = fma2(A0.x, axx[k], fma2(A0.y, ayy[k], fma2(B0.x, azz[k], B0.y)));
            double e1 = fma2(A1.x, axx[k], fma2(A1.y, ayy[k], fma2(B1.x, azz[k], B1.y)));
            double e2 = fma2(A2.x, axx[k], fma2(A2.y, ayy[k], fma2(B2.x, azz[k], B2.y)));
            double e3 = fma2(A3.x, axx[k], fma2(A3.y, ayy[k], fma2(B3.x, azz[k], B3.y)));
            mp[k] = min2(min2(mp[k], e0), min2(e1, min2(e2, e3)));
        }
    }

    #pragma unroll
    for (int k = 0; k < HREG; k++) {
        int h = t + k * THREADS;
        if (h < NH) {
            float d2 = asq[k] + fminf(lo2(mp[k]), hi2(mp[k]));
            unsigned key = ~__float_as_uint(fmaxf(d2, 0.f));
            atomicMax(&g_dmin[b * NH + h], key);     // REDG.MAX (no return)
        }
    }

    // ---- ticket: last block finalizes ----
    __threadfence();                                  // publish our REDG ops
    __shared__ int s_last;
    if (t == 0) {
        int ticket = atomicAdd(&g_ticket, 1);
        s_last = (ticket == NBLOCKS - 1) ? 1 : 0;
    }
    __syncthreads();
    if (!s_last) return;
    __threadfence();                                  // acquire: see all blocks' mins

    float sum_d = 0.f, pen_sum = 0.f, att_sum = 0.f;
    int   pen_cnt = 0, att_cnt = 0;

    for (int i = t; i < NTOT; i += THREADS) {
        unsigned key = g_dmin[i];
        g_dmin[i] = 0u;                               // reset for next replay
        float d2 = __uint_as_float(~key);
        float d  = sqrtf(d2);                         // d2 already clamped >= 0
        sum_d += d;
        if (d < 0.005f) {
            float tt = 0.005f - d;
            pen_sum += tt * tt;
            pen_cnt++;
        }
        int h = i % NH;
        bool is_contact = false;
        #pragma unroll
        for (int j = 0; j < 10; j++) is_contact |= (h == c_contact_idx[j]);
        if (is_contact && d > 0.005f && d < 0.01f) {
            att_sum += d * d;
            att_cnt++;
        }
    }

    __shared__ float s_f[3][5];
    __shared__ int   s_i[2][5];
    const unsigned FULL = 0xffffffffu;
    for (int off = 16; off > 0; off >>= 1) {
        sum_d   += __shfl_down_sync(FULL, sum_d,   off);
        pen_sum += __shfl_down_sync(FULL, pen_sum, off);
        att_sum += __shfl_down_sync(FULL, att_sum, off);
        pen_cnt += __shfl_down_sync(FULL, pen_cnt, off);
        att_cnt += __shfl_down_sync(FULL, att_cnt, off);
    }
    int wid = t >> 5, lid = t & 31;
    if (lid == 0) {
        s_f[0][wid] = sum_d; s_f[1][wid] = pen_sum; s_f[2][wid] = att_sum;
        s_i[0][wid] = pen_cnt; s_i[1][wid] = att_cnt;
    }
    __syncthreads();
    if (t == 0) {
        float tsum = 0.f, tpen = 0.f, tatt = 0.f;
        int   cpen = 0, catt = 0;
        #pragma unroll
        for (int w = 0; w < 5; w++) {
            tsum += s_f[0][w]; tpen += s_f[1][w]; tatt += s_f[2][w];
            cpen += s_i[0][w]; catt += s_i[1][w];
        }
        float pen_loss = (cpen > 0) ? tpen / (float)cpen : 0.f;
        float att_loss = (catt > 0) ? tatt / (float)catt : 0.f;
        out[0] = 100.f * pen_loss + 10.f * att_loss;
        out[1] = pen_loss;
        out[2] = att_loss;
        out[3] = tsum / (float)NTOT;
        out[4] = (float)catt;   // num_contacts
        out[5] = (float)cpen;   // num_penetrations
        g_ticket = 0;           // self-reset for next graph replay
    }
}

extern "C" void kernel_launch(void* const* d_in, const int* in_sizes, int n_in,
                              void* d_out, int out_size)
{
    const float* hand = (const float*)d_in[0];  // [8, 778, 3] f32
    const float* obj  = (const float*)d_in[1];  // [8, 40000, 3] f32
    float* out = (float*)d_out;

    dim3 grid(1, OSLICES, B);                   // 592 blocks = 4/SM, one wave
    mindist_kernel<<<grid, THREADS>>>(hand, obj, out);
    (void)in_sizes; (void)n_in; (void)out_size;
}

// round 12
// speedup vs baseline: 1.2393x; 1.2393x over previous
#include <cuda_runtime.h>
#include <stdint.h>

#define B       8
#define NH      778
#define VOBJ    40000
#define NTOT    (B * NH)          // 6224
#define THREADS 160               // 5 warps
#define HREG    5                 // 160*5 = 800 >= 778
#define OSLICES 74                // 74*8 = 592 blocks = exactly 4 per SM, one wave
#define OSLICE  544               // 74*544 = 40256 >= 40000 (tail clamp-padded)
#define NPAIRS  272               // compile-time trip count, 272 = 4*68
#define RTHREADS 800              // 25 warps: one thread per hand vert

__constant__ int c_contact_idx[10] = {745, 317, 444, 556, 673, 95, 182, 234, 279, 320};

// running min over slices, stored as COMPLEMENTED d^2 bits:
//   key = ~__float_as_uint(d2), d2 >= 0  ->  max(key) == min(d2)
// zero-initialized at module load; reduce re-zeros after reading -> replay-safe.
__device__ unsigned int g_dmin[NTOT];
// per-batch partial stats (fixed slots -> deterministic ordered combine)
__device__ float g_red_f[B * 3];
__device__ int   g_red_i[B * 2];
__device__ int   g_ticket;         // zero-init; finalizer resets to 0

// ---- zero-cost f32x2 <-> double bitcasts (register aliasing, no MOV) ----
__device__ __forceinline__ double pk2(float lo, float hi) {
    return __hiloint2double(__float_as_int(hi), __float_as_int(lo));
}
__device__ __forceinline__ float lo2(double v) { return __int_as_float(__double2loint(v)); }
__device__ __forceinline__ float hi2(double v) { return __int_as_float(__double2hiint(v)); }
__device__ __forceinline__ double fma2(double a, double b, double c) {
    double d;
    asm("fma.rn.f32x2 %0, %1, %2, %3;" : "=d"(d) : "d"(a), "d"(b), "d"(c));
    return d;
}
// packed min via two scalar FMNMX on aliased halves
__device__ __forceinline__ double min2(double a, double b) {
    return pk2(fminf(lo2(a), lo2(b)), fminf(hi2(a), hi2(b)));
}

__global__ __launch_bounds__(THREADS, 4) void mindist_kernel(
    const float* __restrict__ hand, const float* __restrict__ obj)
{
    const int b     = blockIdx.z;
    const int slice = blockIdx.y;
    const int t     = threadIdx.x;

    // each thread owns HREG hand verts: h = t + k*THREADS (coalesced loads)
    double axx[HREG], ayy[HREG], azz[HREG];
    float asq[HREG];
    #pragma unroll
    for (int k = 0; k < HREG; k++) {
        int h  = t + k * THREADS;
        int hc = (h < NH) ? h : 0;          // clamp: spare lanes recompute vert 0
        const float* hp = hand + ((size_t)b * NH + hc) * 3;
        float ax = hp[0], ay = hp[1], az = hp[2];
        asq[k] = fmaf(ax, ax, fmaf(ay, ay, az * az));
        axx[k] = pk2(ax, ax);
        ayy[k] = pk2(ay, ay);
        azz[k] = pk2(az, az);
    }

    // packed-pair SoA: shA[p]={(-2x0,-2x1),(-2y0,-2y1)}, shB[p]={(-2z0,-2z1),(bsq0,bsq1)}
    __shared__ double2 shA[NPAIRS];
    __shared__ double2 shB[NPAIRS];

    const int o0 = slice * OSLICE;

    // tile fill (272 pairs / 160 threads = 2 rounds); pad-by-clamp
    for (int k = t; k < NPAIRS; k += THREADS) {
        int pidx = o0 + k * 2;
        pidx = (pidx <= VOBJ - 2) ? pidx : (VOBJ - 2);
        const float* op = obj + ((size_t)b * VOBJ + pidx) * 3;
        float2 p01 = *(const float2*)(op + 0);   // x0 y0
        float2 p23 = *(const float2*)(op + 2);   // z0 x1
        float2 p45 = *(const float2*)(op + 4);   // y1 z1
        float x0 = p01.x, y0 = p01.y, z0 = p23.x;
        float x1 = p23.y, y1 = p45.x, z1 = p45.y;
        float w0 = fmaf(x0, x0, fmaf(y0, y0, z0 * z0));
        float w1 = fmaf(x1, x1, fmaf(y1, y1, z1 * z1));
        double2 A, Bv;
        A.x  = pk2(-2.f * x0, -2.f * x1);
        A.y  = pk2(-2.f * y0, -2.f * y1);
        Bv.x = pk2(-2.f * z0, -2.f * z1);
        Bv.y = pk2(w0, w1);
        shA[k] = A;
        shB[k] = Bv;
    }
    __syncthreads();

    double mp[HREG];                         // packed running mins
    #pragma unroll
    for (int k = 0; k < HREG; k++) mp[k] = pk2(3.4e38f, 3.4e38f);

    // 4-wide window: hoisted loads, k-outer for operand reuse, 4 chains ILP
    for (int p = 0; p < NPAIRS; p += 4) {
        double2 A0 = shA[p + 0], B0 = shB[p + 0];
        double2 A1 = shA[p + 1], B1 = shB[p + 1];
        double2 A2 = shA[p + 2], B2 = shB[p + 2];
        double2 A3 = shA[p + 3], B3 = shB[p + 3];
        #pragma unroll
        for (int k = 0; k < HREG; k++) {
            double e0 = fma2(A0.x, axx[k], fma2(A0.y, ayy[k], fma2(B0.x, azz[k], B0.y)));
            double e1 = fma2(A1.x, axx[k], fma2(A1.y, ayy[k], fma2(B1.x, azz[k], B1.y)));
            double e2 = fma2(A2.x, axx[k], fma2(A2.y, ayy[k], fma2(B2.x, azz[k], B2.y)));
            double e3 = fma2(A3.x, axx[k], fma2(A3.y, ayy[k], fma2(B3.x, azz[k], B3.y)));
            mp[k] = min2(min2(mp[k], e0), min2(e1, min2(e2, e3)));
        }
    }

    #pragma unroll
    for (int k = 0; k < HREG; k++) {
        int h = t + k * THREADS;
        if (h < NH) {
            float d2 = asq[k] + fminf(lo2(mp[k]), hi2(mp[k]));
            unsigned key = ~__float_as_uint(fmaxf(d2, 0.f));
            atomicMax(&g_dmin[b * NH + h], key);     // REDG.MAX (no return)
        }
    }
}

// 8 blocks (one per batch), 800 threads (one per hand vert); last block combines
__global__ __launch_bounds__(RTHREADS) void reduce_kernel(float* __restrict__ out)
{
    const int b   = blockIdx.x;
    const int tid = threadIdx.x;

    float sum_d = 0.f, pen_sum = 0.f, att_sum = 0.f;
    int   pen_cnt = 0, att_cnt = 0;

    if (tid < NH) {
        const int i = b * NH + tid;
        unsigned key = g_dmin[i];
        g_dmin[i] = 0u;                      // reset for next replay
        float d = sqrtf(__uint_as_float(~key));  // d2 already clamped >= 0
        sum_d = d;
        if (d < 0.005f) {
            float tt = 0.005f - d;
            pen_sum = tt * tt;
            pen_cnt = 1;
        }
        bool is_contact = false;
        #pragma unroll
        for (int j = 0; j < 10; j++) is_contact |= (tid == c_contact_idx[j]);
        if (is_contact && d > 0.005f && d < 0.01f) {
            att_sum = d * d;
            att_cnt = 1;
        }
    }

    __shared__ float s_f[3][25];
    __shared__ int   s_i[2][25];
    const unsigned FULL = 0xffffffffu;
    for (int off = 16; off > 0; off >>= 1) {
        sum_d   += __shfl_down_sync(FULL, sum_d,   off);
        pen_sum += __shfl_down_sync(FULL, pen_sum, off);
        att_sum += __shfl_down_sync(FULL, att_sum, off);
        pen_cnt += __shfl_down_sync(FULL, pen_cnt, off);
        att_cnt += __shfl_down_sync(FULL, att_cnt, off);
    }
    int wid = tid >> 5, lid = tid & 31;
    if (lid == 0) {
        s_f[0][wid] = sum_d; s_f[1][wid] = pen_sum; s_f[2][wid] = att_sum;
        s_i[0][wid] = pen_cnt; s_i[1][wid] = att_cnt;
    }
    __syncthreads();

    if (tid == 0) {
        float a = 0.f, c = 0.f, e = 0.f;
        int   p = 0, q = 0;
        #pragma unroll
        for (int w = 0; w < 25; w++) {
            a += s_f[0][w]; c += s_f[1][w]; e += s_f[2][w];
            p += s_i[0][w]; q += s_i[1][w];
        }
        g_red_f[b * 3 + 0] = a;
        g_red_f[b * 3 + 1] = c;
        g_red_f[b * 3 + 2] = e;
        g_red_i[b * 2 + 0] = p;
        g_red_i[b * 2 + 1] = q;
        __threadfence();
        int ticket = atomicAdd(&g_ticket, 1);
        if (ticket == B - 1) {
            float tsum = 0.f, tpen = 0.f, tatt = 0.f;
            int   cpen = 0, catt = 0;
            #pragma unroll
            for (int r = 0; r < B; r++) {        // fixed order -> deterministic
                tsum += g_red_f[r * 3 + 0];
                tpen += g_red_f[r * 3 + 1];
                tatt += g_red_f[r * 3 + 2];
                cpen += g_red_i[r * 2 + 0];
                catt += g_red_i[r * 2 + 1];
            }
            float pen_loss = (cpen > 0) ? tpen / (float)cpen : 0.f;
            float att_loss = (catt > 0) ? tatt / (float)catt : 0.f;
            out[0] = 100.f * pen_loss + 10.f * att_loss;
            out[1] = pen_loss;
            out[2] = att_loss;
            out[3] = tsum / (float)NTOT;
            out[4] = (float)catt;   // num_contacts
            out[5] = (float)cpen;   // num_penetrations
            g_ticket = 0;           // self-reset for next graph replay
        }
    }
}

extern "C" void kernel_launch(void* const* d_in, const int* in_sizes, int n_in,
                              void* d_out, int out_size)
{
    const float* hand = (const float*)d_in[0];  // [8, 778, 3] f32
    const float* obj  = (const float*)d_in[1];  // [8, 40000, 3] f32
    float* out = (float*)d_out;

    dim3 grid(1, OSLICES, B);                   // 592 blocks = 4/SM, one wave
    mindist_kernel<<<grid, THREADS>>>(hand, obj);
    reduce_kernel<<<B, RTHREADS>>>(out);
    (void)in_sizes; (void)n_in; (void)out_size;
}